// round 9
// baseline (speedup 1.0000x reference)
#include <cuda_runtime.h>
#include <stdint.h>

#define NN 16384
#define DD 32
#define WPR (NN / 32)     // 512 u32 per dedup-bitmask row
#define LCAP 256          // per-node list capacity

// Dedup bitmask (32 MB) + deduped adjacency lists + counters.
// Zero at module load; agg_kernel restores bitmask+counter state every launch.
// g_list entries are always valid node ids; stale ones masked by zero weight.
__device__ uint32_t g_bits[(size_t)NN * WPR];
__device__ int g_list[(size_t)NN * LCAP];
__device__ int g_cnt[NN];
// Pre-transformed features: y = x @ W_agg^T,  z = x @ W_upd^T + b_agg + b_upd
__device__ float g_y[(size_t)NN * DD];
__device__ float g_z[(size_t)NN * DD];

// 8 edges per thread: 4x LDG.128 index loads, 16 INDEPENDENT atomicOr
// issued back-to-back before any dependent consumer (MLP=16).
__global__ void __launch_bounds__(256) build_kernel(const int* __restrict__ src,
                                                    const int* __restrict__ dst,
                                                    int E8) {
    int t = blockIdx.x * blockDim.x + threadIdx.x;
    if (t >= E8) return;
    int4 sa = __ldg(reinterpret_cast<const int4*>(src) + 2 * t);
    int4 sb = __ldg(reinterpret_cast<const int4*>(src) + 2 * t + 1);
    int4 da = __ldg(reinterpret_cast<const int4*>(dst) + 2 * t);
    int4 db = __ldg(reinterpret_cast<const int4*>(dst) + 2 * t + 1);

    int s[8] = {sa.x, sa.y, sa.z, sa.w, sb.x, sb.y, sb.z, sb.w};
    int d[8] = {da.x, da.y, da.z, da.w, db.x, db.y, db.z, db.w};

    unsigned oldf[8], oldb[8];
#pragma unroll
    for (int i = 0; i < 8; i++)
        oldf[i] = atomicOr(&g_bits[(size_t)s[i] * WPR + (d[i] >> 5)], 1u << (d[i] & 31));
#pragma unroll
    for (int i = 0; i < 8; i++)
        oldb[i] = atomicOr(&g_bits[(size_t)d[i] * WPR + (s[i] >> 5)], 1u << (s[i] & 31));

#pragma unroll
    for (int i = 0; i < 8; i++) {
        if (!(oldf[i] & (1u << (d[i] & 31)))) {
            int p = atomicAdd(&g_cnt[s[i]], 1);
            if (p < LCAP) g_list[(size_t)s[i] * LCAP + p] = d[i];
        }
        if (!(oldb[i] & (1u << (s[i] & 31)))) {
            int p = atomicAdd(&g_cnt[d[i]], 1);
            if (p < LCAP) g_list[(size_t)d[i] * LCAP + p] = s[i];
        }
    }
}

// y[r] = x[r] @ W_agg^T ; z[r] = x[r] @ W_upd^T + (b_agg + b_upd).
// One warp per row; x row distributed via shfl, weights via conflict-free LDS.
__global__ void __launch_bounds__(256) transform_kernel(const float* __restrict__ x,
                                                        const float* __restrict__ W_agg,
                                                        const float* __restrict__ b_agg,
                                                        const float* __restrict__ W_upd,
                                                        const float* __restrict__ b_upd) {
    __shared__ float WaggT[DD * DD];   // [d][c] = W_agg[c][d]
    __shared__ float WupdT[DD * DD];
    __shared__ float bsum[DD];

    int tid = threadIdx.x;
    for (int i = tid; i < DD * DD; i += blockDim.x) {
        int c = i >> 5, d = i & 31;
        WaggT[d * DD + c] = W_agg[i];
        WupdT[d * DD + c] = W_upd[i];
    }
    if (tid < DD) bsum[tid] = b_agg[tid] + b_upd[tid];
    __syncthreads();

    int warp = tid >> 5;
    int lane = tid & 31;   // = output channel c
    int row  = blockIdx.x * 8 + warp;

    float xv = x[(size_t)row * DD + lane];
    float ya = 0.0f;
    float za = bsum[lane];
#pragma unroll
    for (int d = 0; d < DD; d++) {
        float xd = __shfl_sync(0xffffffffu, xv, d);
        ya = fmaf(xd, WaggT[d * DD + lane], ya);
        za = fmaf(xd, WupdT[d * DD + lane], za);
    }
    g_y[(size_t)row * DD + lane] = ya;
    g_z[(size_t)row * DD + lane] = za;
}

// One warp per node: gather-sum y rows (4 lane-groups of 8; one LDG.128 = 4
// neighbor rows), clear dedup state, xor-reduce, add z, store float4.
// NO weights, NO epilogue matvec, NO __syncthreads.
__global__ void __launch_bounds__(256) agg_kernel(float* __restrict__ out) {
    int tid  = threadIdx.x;
    int warp = tid >> 5;
    int lane = tid & 31;
    int row  = blockIdx.x * 8 + warp;

    const int* lst = g_list + (size_t)row * LCAP;

    // Front-batched independent loads (addresses independent of cnt).
    int i0 = __ldg(lst + lane);
    int i1 = __ldg(lst + 32 + lane);
    int i2 = __ldg(lst + 64 + lane);
    int cnt = g_cnt[row];
    cnt = cnt < LCAP ? cnt : LCAP;
    if (lane == 0) g_cnt[row] = 0;        // reset for next replay

    int g = lane >> 3;        // gather group 0..3
    int q = lane & 7;         // float4 slot within a 128B row

    const float4* y4 = reinterpret_cast<const float4*>(g_y);
    float4 A0 = make_float4(0.f, 0.f, 0.f, 0.f);
    float4 A1 = A0;

    // ---- Slots 0..63: fully branchless, 16 independent LDG.128 (MLP 16).
#pragma unroll
    for (int u = 0; u < 8; u++) {
        int slot = (u << 2) + g;
        int j = __shfl_sync(0xffffffffu, i0, slot);
        float w = (slot < cnt) ? 1.0f : 0.0f;
        float4 v = y4[(size_t)j * 8 + q];
        float4& A = (u & 1) ? A1 : A0;
        A.x = fmaf(w, v.x, A.x); A.y = fmaf(w, v.y, A.y);
        A.z = fmaf(w, v.z, A.z); A.w = fmaf(w, v.w, A.w);
    }
#pragma unroll
    for (int u = 0; u < 8; u++) {
        int slot = (u << 2) + g;
        int j = __shfl_sync(0xffffffffu, i1, slot);
        float w = (32 + slot < cnt) ? 1.0f : 0.0f;
        float4 v = y4[(size_t)j * 8 + q];
        float4& A = (u & 1) ? A1 : A0;
        A.x = fmaf(w, v.x, A.x); A.y = fmaf(w, v.y, A.y);
        A.z = fmaf(w, v.z, A.z); A.w = fmaf(w, v.w, A.w);
    }

    // ---- Slots 64..95 (about half of rows enter).
    if (cnt > 64) {
        int ng = cnt - 64;  ng = ng > 32 ? 32 : ng;
        int nu = (ng + 3) >> 2;
#pragma unroll
        for (int u = 0; u < 8; u++) {
            if (u < nu) {
                int slot = (u << 2) + g;
                int j = __shfl_sync(0xffffffffu, i2, slot);
                float w = (slot < ng) ? 1.0f : 0.0f;
                float4 v = y4[(size_t)j * 8 + q];
                float4& A = (u & 1) ? A1 : A0;
                A.x = fmaf(w, v.x, A.x); A.y = fmaf(w, v.y, A.y);
                A.z = fmaf(w, v.z, A.z); A.w = fmaf(w, v.w, A.w);
            }
        }
    }

    // ---- Rare tail: slots 96..255 (Poisson(64) -> essentially never).
    for (int k = 3; k < 8; k++) {
        int base = k << 5;
        if (base >= cnt) break;
        int ik = __ldg(lst + base + lane);
        int ng = cnt - base;  ng = ng > 32 ? 32 : ng;
        int nu = (ng + 3) >> 2;
        for (int u = 0; u < 8; u++) {
            if (u < nu) {
                int slot = (u << 2) + g;
                int j = __shfl_sync(0xffffffffu, ik, slot);
                float w = (slot < ng) ? 1.0f : 0.0f;
                float4 v = y4[(size_t)j * 8 + q];
                A0.x = fmaf(w, v.x, A0.x); A0.y = fmaf(w, v.y, A0.y);
                A0.z = fmaf(w, v.z, A0.z); A0.w = fmaf(w, v.w, A0.w);
            }
        }
    }

    // Clear this row's dedup bits for the next replay (gathers already issued).
    {
        uint4* rv = reinterpret_cast<uint4*>(g_bits + (size_t)row * WPR);
        const uint4 z = make_uint4(0u, 0u, 0u, 0u);
        rv[lane]      = z;
        rv[lane + 32] = z;
        rv[lane + 64] = z;
        rv[lane + 96] = z;
    }

    // Reduce 2 accumulators, then across the 4 lane-groups (xor 8, xor 16).
    float4 s;
    s.x = A0.x + A1.x;  s.y = A0.y + A1.y;
    s.z = A0.z + A1.z;  s.w = A0.w + A1.w;
#pragma unroll
    for (int off = 8; off <= 16; off <<= 1) {
        s.x += __shfl_xor_sync(0xffffffffu, s.x, off);
        s.y += __shfl_xor_sync(0xffffffffu, s.y, off);
        s.z += __shfl_xor_sync(0xffffffffu, s.z, off);
        s.w += __shfl_xor_sync(0xffffffffu, s.w, off);
    }

    // out[row] = msg + z[row]; lanes 0..7 store the row as 8 float4.
    if (lane < 8) {
        float4 zc = *reinterpret_cast<const float4*>(g_z + (size_t)row * DD + (q << 2));
        s.x += zc.x; s.y += zc.y; s.z += zc.z; s.w += zc.w;
        reinterpret_cast<float4*>(out)[(size_t)row * 8 + q] = s;
    }
}

extern "C" void kernel_launch(void* const* d_in, const int* in_sizes, int n_in,
                              void* d_out, int out_size) {
    const float* x     = (const float*)d_in[0];
    const int*   ei    = (const int*)d_in[1];     // [2, E]: row0=src, row1=dst
    const float* W_agg = (const float*)d_in[2];
    const float* b_agg = (const float*)d_in[3];
    const float* W_upd = (const float*)d_in[4];
    const float* b_upd = (const float*)d_in[5];
    float* out = (float*)d_out;

    int E  = in_sizes[1] / 2;
    int E8 = E / 8;                               // E = 524288, divisible by 8

    build_kernel<<<(E8 + 255) / 256, 256>>>(ei, ei + E, E8);
    transform_kernel<<<NN / 8, 256>>>(x, W_agg, b_agg, W_upd, b_upd);
    agg_kernel<<<NN / 8, 256>>>(out);
}

// round 10
// speedup vs baseline: 1.1463x; 1.1463x over previous
#include <cuda_runtime.h>
#include <stdint.h>

#define NN 16384
#define DD 32
#define WPR (NN / 32)     // 512 u32 per dedup-bitmask row
#define LCAP 256          // per-node list capacity

// Canonical-pair dedup bitmask: bit for pair {a,b} (a<=b) lives at
// g_bits[a*WPR + (b>>5)]. Zero at module load; agg clears exactly the words
// its row set (targeted clear). Lists hold deduped neighbors both directions.
__device__ uint32_t g_bits[(size_t)NN * WPR];
__device__ int g_list[(size_t)NN * LCAP];
__device__ int g_cnt[NN];

// 8 edges per thread. ONE canonical atomicOr per edge (dedup decision shared
// by both directions), front-batched for MLP=8, then dependent list appends.
__global__ void __launch_bounds__(256) build_kernel(const int* __restrict__ src,
                                                    const int* __restrict__ dst,
                                                    int E8) {
    int t = blockIdx.x * blockDim.x + threadIdx.x;
    if (t >= E8) return;
    int4 sa = __ldg(reinterpret_cast<const int4*>(src) + 2 * t);
    int4 sb = __ldg(reinterpret_cast<const int4*>(src) + 2 * t + 1);
    int4 da = __ldg(reinterpret_cast<const int4*>(dst) + 2 * t);
    int4 db = __ldg(reinterpret_cast<const int4*>(dst) + 2 * t + 1);

    int s[8] = {sa.x, sa.y, sa.z, sa.w, sb.x, sb.y, sb.z, sb.w};
    int d[8] = {da.x, da.y, da.z, da.w, db.x, db.y, db.z, db.w};

    int a[8], b[8];
#pragma unroll
    for (int i = 0; i < 8; i++) {
        a[i] = s[i] < d[i] ? s[i] : d[i];
        b[i] = s[i] < d[i] ? d[i] : s[i];
    }

    unsigned old[8];
#pragma unroll
    for (int i = 0; i < 8; i++)
        old[i] = atomicOr(&g_bits[(size_t)a[i] * WPR + (b[i] >> 5)], 1u << (b[i] & 31));

#pragma unroll
    for (int i = 0; i < 8; i++) {
        if (!(old[i] & (1u << (b[i] & 31)))) {    // first time pair {a,b} seen
            int p = atomicAdd(&g_cnt[a[i]], 1);
            if (p < LCAP) g_list[(size_t)a[i] * LCAP + p] = b[i];
            if (a[i] != b[i]) {
                p = atomicAdd(&g_cnt[b[i]], 1);
                if (p < LCAP) g_list[(size_t)b[i] * LCAP + p] = a[i];
            }
        }
    }
}

// One warp per node (R8 structure). Unguarded front-batched index preload,
// branchless 16-LDG gather block for slots 0..63, guarded 64..95, rare tail.
// Bitmask cleanup is TARGETED: only words holding this row's set bits.
__global__ void __launch_bounds__(256, 6) agg_kernel(const float* __restrict__ x,
                                                     const float* __restrict__ W_agg,
                                                     const float* __restrict__ b_agg,
                                                     const float* __restrict__ W_upd,
                                                     const float* __restrict__ b_upd,
                                                     float* __restrict__ out) {
    __shared__ float WaggT[DD * DD];   // [d][c] = W_agg[c][d]
    __shared__ float WupdT[DD * DD];
    __shared__ float bsum[DD];
    __shared__ float msgsm[8][DD];
    __shared__ float xsm[8][DD];

    int tid  = threadIdx.x;
    int warp = tid >> 5;
    int lane = tid & 31;
    int row  = blockIdx.x * 8 + warp;

    const int* lst = g_list + (size_t)row * LCAP;

    // Front-batched independent loads: 3 index words + own x row + cnt.
    int i0 = __ldg(lst + lane);
    int i1 = __ldg(lst + 32 + lane);
    int i2 = __ldg(lst + 64 + lane);
    float xown = x[(size_t)row * DD + lane];
    int cnt = g_cnt[row];
    cnt = cnt < LCAP ? cnt : LCAP;
    if (lane == 0) g_cnt[row] = 0;        // reset for next replay

    for (int i = tid; i < DD * DD; i += blockDim.x) {
        int c = i >> 5, d = i & 31;
        WaggT[d * DD + c] = W_agg[i];
        WupdT[d * DD + c] = W_upd[i];
    }
    if (tid < DD) bsum[tid] = b_agg[tid] + b_upd[tid];

    int g = lane >> 3;        // gather group 0..3
    int q = lane & 7;         // float4 slot within a 128B row

    const float4* x4 = reinterpret_cast<const float4*>(x);
    float4 A0 = make_float4(0.f, 0.f, 0.f, 0.f);
    float4 A1 = A0;

    // ---- Block 1: slots 0..63, fully branchless (16 independent LDG.128).
#pragma unroll
    for (int u = 0; u < 8; u++) {
        int slot = (u << 2) + g;
        int j = __shfl_sync(0xffffffffu, i0, slot);
        float w = (slot < cnt) ? 1.0f : 0.0f;
        float4 v = x4[(size_t)j * 8 + q];
        float4& A = (u & 1) ? A1 : A0;
        A.x = fmaf(w, v.x, A.x); A.y = fmaf(w, v.y, A.y);
        A.z = fmaf(w, v.z, A.z); A.w = fmaf(w, v.w, A.w);
    }
#pragma unroll
    for (int u = 0; u < 8; u++) {
        int slot = (u << 2) + g;
        int j = __shfl_sync(0xffffffffu, i1, slot);
        float w = (32 + slot < cnt) ? 1.0f : 0.0f;
        float4 v = x4[(size_t)j * 8 + q];
        float4& A = (u & 1) ? A1 : A0;
        A.x = fmaf(w, v.x, A.x); A.y = fmaf(w, v.y, A.y);
        A.z = fmaf(w, v.z, A.z); A.w = fmaf(w, v.w, A.w);
    }

    // ---- Block 2: slots 64..95 (about half of rows enter).
    if (cnt > 64) {
        int ng = cnt - 64;  ng = ng > 32 ? 32 : ng;
        int nu = (ng + 3) >> 2;
#pragma unroll
        for (int u = 0; u < 8; u++) {
            if (u < nu) {
                int slot = (u << 2) + g;
                int j = __shfl_sync(0xffffffffu, i2, slot);
                float w = (slot < ng) ? 1.0f : 0.0f;
                float4 v = x4[(size_t)j * 8 + q];
                float4& A = (u & 1) ? A1 : A0;
                A.x = fmaf(w, v.x, A.x); A.y = fmaf(w, v.y, A.y);
                A.z = fmaf(w, v.z, A.z); A.w = fmaf(w, v.w, A.w);
            }
        }
    }

    // ---- Rare tail: slots 96..255 (Poisson(64): ~0.5 nodes chip-wide).
    for (int k = 3; k < 8; k++) {
        int base = k << 5;
        if (base >= cnt) break;
        int ik = __ldg(lst + base + lane);
        // targeted clear for tail entries owned by this row
        if (base + lane < cnt && ik >= row)
            g_bits[(size_t)row * WPR + (ik >> 5)] = 0u;
        int ng = cnt - base;  ng = ng > 32 ? 32 : ng;
        int nu = (ng + 3) >> 2;
        for (int u = 0; u < 8; u++) {
            if (u < nu) {
                int slot = (u << 2) + g;
                int j = __shfl_sync(0xffffffffu, ik, slot);
                float w = (slot < ng) ? 1.0f : 0.0f;
                float4 v = x4[(size_t)j * 8 + q];
                A0.x = fmaf(w, v.x, A0.x); A0.y = fmaf(w, v.y, A0.y);
                A0.z = fmaf(w, v.z, A0.z); A0.w = fmaf(w, v.w, A0.w);
            }
        }
    }

    // ---- Targeted bitmask clear: the only set bits in row `row` are pairs
    // (row, j>=row); zero exactly those words (<=3 scalar stores per lane).
    {
        uint32_t* bits_row = g_bits + (size_t)row * WPR;
        if (lane      < cnt && i0 >= row) bits_row[i0 >> 5] = 0u;
        if (32 + lane < cnt && i1 >= row) bits_row[i1 >> 5] = 0u;
        if (64 + lane < cnt && i2 >= row) bits_row[i2 >> 5] = 0u;
    }

    __syncthreads();   // weights/bias smem ready (overlapped with gather latency)

    // Reduce 2 accumulators, then across the 4 lane-groups (xor 8, xor 16).
    float4 s;
    s.x = A0.x + A1.x;  s.y = A0.y + A1.y;
    s.z = A0.z + A1.z;  s.w = A0.w + A1.w;
#pragma unroll
    for (int off = 8; off <= 16; off <<= 1) {
        s.x += __shfl_xor_sync(0xffffffffu, s.x, off);
        s.y += __shfl_xor_sync(0xffffffffu, s.y, off);
        s.z += __shfl_xor_sync(0xffffffffu, s.z, off);
        s.w += __shfl_xor_sync(0xffffffffu, s.w, off);
    }
    if (lane < 8)
        *reinterpret_cast<float4*>(&msgsm[warp][q << 2]) = s;
    xsm[warp][lane] = xown;
    __syncwarp();

    // Fused epilogue: out[row][c] = sum_d msg[d]*W_agg[c][d] + x[row][d]*W_upd[c][d] + b
    float o = bsum[lane];
#pragma unroll
    for (int d = 0; d < DD; d++) {
        o = fmaf(msgsm[warp][d], WaggT[d * DD + lane],
            fmaf(xsm[warp][d],  WupdT[d * DD + lane], o));
    }
    out[(size_t)row * DD + lane] = o;
}

extern "C" void kernel_launch(void* const* d_in, const int* in_sizes, int n_in,
                              void* d_out, int out_size) {
    const float* x     = (const float*)d_in[0];
    const int*   ei    = (const int*)d_in[1];     // [2, E]: row0=src, row1=dst
    const float* W_agg = (const float*)d_in[2];
    const float* b_agg = (const float*)d_in[3];
    const float* W_upd = (const float*)d_in[4];
    const float* b_upd = (const float*)d_in[5];
    float* out = (float*)d_out;

    int E  = in_sizes[1] / 2;
    int E8 = E / 8;                               // E = 524288, divisible by 8

    build_kernel<<<(E8 + 255) / 256, 256>>>(ei, ei + E, E8);
    agg_kernel<<<NN / 8, 256>>>(x, W_agg, b_agg, W_upd, b_upd, out);
}

// round 11
// speedup vs baseline: 1.3905x; 1.2130x over previous
#include <cuda_runtime.h>
#include <stdint.h>

#define NN 16384
#define DD 32
#define WPR (NN / 32)     // 512 u32 per dedup-bitmask row
#define LCAP 256          // per-node list capacity

// Canonical-pair dedup bitmask: bit for pair {a,b} (a<=b) lives at
// g_bits[a*WPR + (b>>5)]. All bits of row r are cleared by row r's warp in
// agg (blanket 2KB clear). Lists hold deduped neighbors, both directions.
__device__ uint32_t g_bits[(size_t)NN * WPR];
__device__ int g_list[(size_t)NN * LCAP];
__device__ int g_cnt[NN];

// 8 edges per thread. ONE canonical atomicOr per edge (dedup decision shared
// by both directions), front-batched for MLP=8, then dependent list appends.
__global__ void __launch_bounds__(256) build_kernel(const int* __restrict__ src,
                                                    const int* __restrict__ dst,
                                                    int E8) {
    int t = blockIdx.x * blockDim.x + threadIdx.x;
    if (t >= E8) return;
    int4 sa = __ldg(reinterpret_cast<const int4*>(src) + 2 * t);
    int4 sb = __ldg(reinterpret_cast<const int4*>(src) + 2 * t + 1);
    int4 da = __ldg(reinterpret_cast<const int4*>(dst) + 2 * t);
    int4 db = __ldg(reinterpret_cast<const int4*>(dst) + 2 * t + 1);

    int s[8] = {sa.x, sa.y, sa.z, sa.w, sb.x, sb.y, sb.z, sb.w};
    int d[8] = {da.x, da.y, da.z, da.w, db.x, db.y, db.z, db.w};

    int a[8], b[8];
#pragma unroll
    for (int i = 0; i < 8; i++) {
        a[i] = s[i] < d[i] ? s[i] : d[i];
        b[i] = s[i] < d[i] ? d[i] : s[i];
    }

    unsigned old[8];
#pragma unroll
    for (int i = 0; i < 8; i++)
        old[i] = atomicOr(&g_bits[(size_t)a[i] * WPR + (b[i] >> 5)], 1u << (b[i] & 31));

#pragma unroll
    for (int i = 0; i < 8; i++) {
        if (!(old[i] & (1u << (b[i] & 31)))) {    // first time pair {a,b} seen
            int p = atomicAdd(&g_cnt[a[i]], 1);
            if (p < LCAP) g_list[(size_t)a[i] * LCAP + p] = b[i];
            if (a[i] != b[i]) {
                p = atomicAdd(&g_cnt[b[i]], 1);
                if (p < LCAP) g_list[(size_t)b[i] * LCAP + p] = a[i];
            }
        }
    }
}

// One warp per node (R8 structure). Unguarded front-batched index preload,
// branchless 16-LDG gather block for slots 0..63, guarded 64..95, rare tail,
// blanket coalesced 2KB bitmask row clear, fused 32x32 epilogue.
__global__ void __launch_bounds__(256, 6) agg_kernel(const float* __restrict__ x,
                                                     const float* __restrict__ W_agg,
                                                     const float* __restrict__ b_agg,
                                                     const float* __restrict__ W_upd,
                                                     const float* __restrict__ b_upd,
                                                     float* __restrict__ out) {
    __shared__ float WaggT[DD * DD];   // [d][c] = W_agg[c][d]
    __shared__ float WupdT[DD * DD];
    __shared__ float bsum[DD];
    __shared__ float msgsm[8][DD];
    __shared__ float xsm[8][DD];

    int tid  = threadIdx.x;
    int warp = tid >> 5;
    int lane = tid & 31;
    int row  = blockIdx.x * 8 + warp;

    const int* lst = g_list + (size_t)row * LCAP;

    // Front-batched independent loads: 3 index words + own x row + cnt.
    int i0 = __ldg(lst + lane);
    int i1 = __ldg(lst + 32 + lane);
    int i2 = __ldg(lst + 64 + lane);
    float xown = x[(size_t)row * DD + lane];
    int cnt = g_cnt[row];
    cnt = cnt < LCAP ? cnt : LCAP;
    if (lane == 0) g_cnt[row] = 0;        // reset for next replay

    for (int i = tid; i < DD * DD; i += blockDim.x) {
        int c = i >> 5, d = i & 31;
        WaggT[d * DD + c] = W_agg[i];
        WupdT[d * DD + c] = W_upd[i];
    }
    if (tid < DD) bsum[tid] = b_agg[tid] + b_upd[tid];

    int g = lane >> 3;        // gather group 0..3
    int q = lane & 7;         // float4 slot within a 128B row

    const float4* x4 = reinterpret_cast<const float4*>(x);
    float4 A0 = make_float4(0.f, 0.f, 0.f, 0.f);
    float4 A1 = A0;

    // ---- Block 1: slots 0..63, fully branchless (16 independent LDG.128).
#pragma unroll
    for (int u = 0; u < 8; u++) {
        int slot = (u << 2) + g;
        int j = __shfl_sync(0xffffffffu, i0, slot);
        float w = (slot < cnt) ? 1.0f : 0.0f;
        float4 v = x4[(size_t)j * 8 + q];
        float4& A = (u & 1) ? A1 : A0;
        A.x = fmaf(w, v.x, A.x); A.y = fmaf(w, v.y, A.y);
        A.z = fmaf(w, v.z, A.z); A.w = fmaf(w, v.w, A.w);
    }
#pragma unroll
    for (int u = 0; u < 8; u++) {
        int slot = (u << 2) + g;
        int j = __shfl_sync(0xffffffffu, i1, slot);
        float w = (32 + slot < cnt) ? 1.0f : 0.0f;
        float4 v = x4[(size_t)j * 8 + q];
        float4& A = (u & 1) ? A1 : A0;
        A.x = fmaf(w, v.x, A.x); A.y = fmaf(w, v.y, A.y);
        A.z = fmaf(w, v.z, A.z); A.w = fmaf(w, v.w, A.w);
    }

    // ---- Block 2: slots 64..95 (about half of rows enter).
    if (cnt > 64) {
        int ng = cnt - 64;  ng = ng > 32 ? 32 : ng;
        int nu = (ng + 3) >> 2;
#pragma unroll
        for (int u = 0; u < 8; u++) {
            if (u < nu) {
                int slot = (u << 2) + g;
                int j = __shfl_sync(0xffffffffu, i2, slot);
                float w = (slot < ng) ? 1.0f : 0.0f;
                float4 v = x4[(size_t)j * 8 + q];
                float4& A = (u & 1) ? A1 : A0;
                A.x = fmaf(w, v.x, A.x); A.y = fmaf(w, v.y, A.y);
                A.z = fmaf(w, v.z, A.z); A.w = fmaf(w, v.w, A.w);
            }
        }
    }

    // ---- Rare tail: slots 96..255 (Poisson(64): ~never; kept for correctness).
    for (int k = 3; k < 8; k++) {
        int base = k << 5;
        if (base >= cnt) break;
        int ik = __ldg(lst + base + lane);
        int ng = cnt - base;  ng = ng > 32 ? 32 : ng;
        int nu = (ng + 3) >> 2;
        for (int u = 0; u < 8; u++) {
            if (u < nu) {
                int slot = (u << 2) + g;
                int j = __shfl_sync(0xffffffffu, ik, slot);
                float w = (slot < ng) ? 1.0f : 0.0f;
                float4 v = x4[(size_t)j * 8 + q];
                A0.x = fmaf(w, v.x, A0.x); A0.y = fmaf(w, v.y, A0.y);
                A0.z = fmaf(w, v.z, A0.z); A0.w = fmaf(w, v.w, A0.w);
            }
        }
    }

    // Blanket clear of this row's 2KB bitmask stripe (coalesced STG.128;
    // covers every canonical-pair bit this row owns).
    {
        uint4* rv = reinterpret_cast<uint4*>(g_bits + (size_t)row * WPR);
        const uint4 z = make_uint4(0u, 0u, 0u, 0u);
        rv[lane]      = z;
        rv[lane + 32] = z;
        rv[lane + 64] = z;
        rv[lane + 96] = z;
    }

    __syncthreads();   // weights/bias smem ready (overlapped with gather latency)

    // Reduce 2 accumulators, then across the 4 lane-groups (xor 8, xor 16).
    float4 s;
    s.x = A0.x + A1.x;  s.y = A0.y + A1.y;
    s.z = A0.z + A1.z;  s.w = A0.w + A1.w;
#pragma unroll
    for (int off = 8; off <= 16; off <<= 1) {
        s.x += __shfl_xor_sync(0xffffffffu, s.x, off);
        s.y += __shfl_xor_sync(0xffffffffu, s.y, off);
        s.z += __shfl_xor_sync(0xffffffffu, s.z, off);
        s.w += __shfl_xor_sync(0xffffffffu, s.w, off);
    }
    if (lane < 8)
        *reinterpret_cast<float4*>(&msgsm[warp][q << 2]) = s;
    xsm[warp][lane] = xown;
    __syncwarp();

    // Fused epilogue: out[row][c] = sum_d msg[d]*W_agg[c][d] + x[row][d]*W_upd[c][d] + b
    float o = bsum[lane];
#pragma unroll
    for (int d = 0; d < DD; d++) {
        o = fmaf(msgsm[warp][d], WaggT[d * DD + lane],
            fmaf(xsm[warp][d],  WupdT[d * DD + lane], o));
    }
    out[(size_t)row * DD + lane] = o;
}

extern "C" void kernel_launch(void* const* d_in, const int* in_sizes, int n_in,
                              void* d_out, int out_size) {
    const float* x     = (const float*)d_in[0];
    const int*   ei    = (const int*)d_in[1];     // [2, E]: row0=src, row1=dst
    const float* W_agg = (const float*)d_in[2];
    const float* b_agg = (const float*)d_in[3];
    const float* W_upd = (const float*)d_in[4];
    const float* b_upd = (const float*)d_in[5];
    float* out = (float*)d_out;

    int E  = in_sizes[1] / 2;
    int E8 = E / 8;                               // E = 524288, divisible by 8

    build_kernel<<<(E8 + 255) / 256, 256>>>(ei, ei + E, E8);
    agg_kernel<<<NN / 8, 256>>>(x, W_agg, b_agg, W_upd, b_upd, out);
}